// round 2
// baseline (speedup 1.0000x reference)
#include <cuda_runtime.h>
#include <math.h>

#define Lnum 2
#define Bnum 32
#define Tnum 2048
#define Hnum 512

// Scratch (static device arrays — allocation-free per harness rules)
__device__ float g_has[Bnum * Hnum];     // ha * 2*log2(e), pre-scaled for ex2
__device__ float g_energy[Bnum * Tnum];  // raw attention energies

__device__ __forceinline__ float ex2a(float x) {
    float y; asm("ex2.approx.f32 %0, %1;" : "=f"(y) : "f"(x)); return y;
}
__device__ __forceinline__ float rcpa(float x) {
    float y; asm("rcp.approx.f32 %0, %1;" : "=f"(y) : "f"(x)); return y;
}

#define C2LOG2E 2.8853900817779268f   // 2*log2(e)
#define LOG2E   1.4426950408889634f

// ---------------------------------------------------------------------------
// Kernel A: ha[b,h] = sum_k mean_L(hidden)[b,k] * Wh[h,k] + bh[h], pre-scaled
// by 2*log2(e) so the energy kernel's tanh arg needs only one FMA.
// ---------------------------------------------------------------------------
__global__ __launch_bounds__(256) void proj_kernel(
    const float* __restrict__ hidden,
    const float* __restrict__ Wh,
    const float* __restrict__ bh)
{
    const int h0 = blockIdx.x * 4;
    __shared__ float s_w[4 * Hnum];
    for (int i = threadIdx.x; i < 4 * Hnum; i += 256)
        s_w[i] = Wh[h0 * Hnum + i];
    __syncthreads();

    const int warp = threadIdx.x >> 5;
    const int lane = threadIdx.x & 31;
    const float* __restrict__ hl0 = hidden;
    const float* __restrict__ hl1 = hidden + Bnum * Hnum;

    for (int r = 0; r < 4; r++) {
        const int b = warp * 4 + r;
        float a0 = 0.f, a1 = 0.f, a2 = 0.f, a3 = 0.f;
        #pragma unroll
        for (int k = lane; k < Hnum; k += 32) {
            float hm = 0.5f * (hl0[b * Hnum + k] + hl1[b * Hnum + k]);
            a0 = fmaf(hm, s_w[0 * Hnum + k], a0);
            a1 = fmaf(hm, s_w[1 * Hnum + k], a1);
            a2 = fmaf(hm, s_w[2 * Hnum + k], a2);
            a3 = fmaf(hm, s_w[3 * Hnum + k], a3);
        }
        #pragma unroll
        for (int off = 16; off; off >>= 1) {
            a0 += __shfl_xor_sync(0xffffffffu, a0, off);
            a1 += __shfl_xor_sync(0xffffffffu, a1, off);
            a2 += __shfl_xor_sync(0xffffffffu, a2, off);
            a3 += __shfl_xor_sync(0xffffffffu, a3, off);
        }
        if (lane == 0) {
            g_has[b * Hnum + h0 + 0] = (a0 + bh[h0 + 0]) * C2LOG2E;
            g_has[b * Hnum + h0 + 1] = (a1 + bh[h0 + 1]) * C2LOG2E;
            g_has[b * Hnum + h0 + 2] = (a2 + bh[h0 + 2]) * C2LOG2E;
            g_has[b * Hnum + h0 + 3] = (a3 + bh[h0 + 3]) * C2LOG2E;
        }
    }
}

// ---------------------------------------------------------------------------
// Kernel B: energy[b,t] = sum_h Wo[h] * tanh(eo[t,b,h] + ha[b,h])
// Streams the 128MB encoder_output exactly once. One warp per t; each lane
// handles 16 H-elements via 4x float4 coalesced loads.
// tanh(x) = (e^{2x}-1)/(e^{2x}+1), e^{2x} = ex2(C*x) with pre-scaled ha.
// ---------------------------------------------------------------------------
__global__ __launch_bounds__(256) void energy_kernel(
    const float* __restrict__ eo,
    const float* __restrict__ Wo)
{
    __shared__ float s_has[Hnum];
    __shared__ float s_wo[Hnum];
    const int b = blockIdx.y;
    const int tbase = blockIdx.x * 64;

    for (int i = threadIdx.x; i < Hnum; i += 256) {
        s_has[i] = g_has[b * Hnum + i];
        s_wo[i]  = Wo[i];
    }
    __syncthreads();

    const int warp = threadIdx.x >> 5;
    const int lane = threadIdx.x & 31;
    const float4* __restrict__ eo4 = (const float4*)eo;

    #pragma unroll 2
    for (int i = 0; i < 8; i++) {
        const int t = tbase + warp * 8 + i;
        const size_t base = ((size_t)t * Bnum + b) * (Hnum / 4);
        float acc = 0.f;
        #pragma unroll
        for (int j = 0; j < 4; j++) {
            const int k4 = j * 32 + lane;
            float4 e  = eo4[base + k4];
            float4 hs = *(const float4*)&s_has[k4 * 4];
            float4 wo = *(const float4*)&s_wo[k4 * 4];

            float arg, ex;
            arg = fmaf(e.x, C2LOG2E, hs.x);
            arg = fminf(fmaxf(arg, -80.f), 80.f);
            ex  = ex2a(arg);
            acc = fmaf((ex - 1.f) * wo.x, rcpa(ex + 1.f), acc);

            arg = fmaf(e.y, C2LOG2E, hs.y);
            arg = fminf(fmaxf(arg, -80.f), 80.f);
            ex  = ex2a(arg);
            acc = fmaf((ex - 1.f) * wo.y, rcpa(ex + 1.f), acc);

            arg = fmaf(e.z, C2LOG2E, hs.z);
            arg = fminf(fmaxf(arg, -80.f), 80.f);
            ex  = ex2a(arg);
            acc = fmaf((ex - 1.f) * wo.z, rcpa(ex + 1.f), acc);

            arg = fmaf(e.w, C2LOG2E, hs.w);
            arg = fminf(fmaxf(arg, -80.f), 80.f);
            ex  = ex2a(arg);
            acc = fmaf((ex - 1.f) * wo.w, rcpa(ex + 1.f), acc);
        }
        #pragma unroll
        for (int off = 16; off; off >>= 1)
            acc += __shfl_xor_sync(0xffffffffu, acc, off);
        if (lane == 0)
            g_energy[b * Tnum + t] = acc;
    }
}

// ---------------------------------------------------------------------------
// Kernel C: ragged masked softmax over T per batch row. bo cancels in
// softmax (uniform additive constant over the valid positions) -> dropped.
//
// enc_len dtype auto-detect (JAX silently downgrades int64->int32 unless
// x64 is enabled, so the buffer may be either):
//   Read the buffer as int32 words. Valid lengths are >= 1, so word[1]==0
//   iff the buffer is little-endian int64 (word[1] is the high half of
//   element 0). Then len[b] = word[2b]; else len[b] = word[b]. The probe
//   read of word[1] is within 128 bytes — in-bounds for both layouts; the
//   strided-by-2 reads happen only when the buffer really is 256 bytes.
// ---------------------------------------------------------------------------
__global__ __launch_bounds__(256) void softmax_kernel(
    const int* __restrict__ enc_len_w,
    float* __restrict__ out)
{
    const int b = blockIdx.x;
    const bool is64 = (enc_len_w[1] == 0);
    const int len = is64 ? enc_len_w[2 * b] : enc_len_w[b];   // in [1, T]

    __shared__ float s_e[Tnum];
    __shared__ float s_red[8];

    const int warp = threadIdx.x >> 5;
    const int lane = threadIdx.x & 31;

    // Pass 1: load energies + masked max
    float m = -3.0e38f;
    for (int t = threadIdx.x; t < Tnum; t += 256) {
        float v = g_energy[b * Tnum + t];
        s_e[t] = v;
        if (t < len) m = fmaxf(m, v);
    }
    #pragma unroll
    for (int off = 16; off; off >>= 1)
        m = fmaxf(m, __shfl_xor_sync(0xffffffffu, m, off));
    if (lane == 0) s_red[warp] = m;
    __syncthreads();
    m = s_red[0];
    #pragma unroll
    for (int i = 1; i < 8; i++) m = fmaxf(m, s_red[i]);
    __syncthreads();

    // Pass 2: exp + sum (only valid positions)
    float s = 0.f;
    for (int t = threadIdx.x; t < Tnum; t += 256) {
        if (t < len) {
            float p = ex2a((s_e[t] - m) * LOG2E);
            s_e[t] = p;
            s += p;
        }
    }
    #pragma unroll
    for (int off = 16; off; off >>= 1)
        s += __shfl_xor_sync(0xffffffffu, s, off);
    if (lane == 0) s_red[warp] = s;
    __syncthreads();
    float tot = 0.f;
    #pragma unroll
    for (int i = 0; i < 8; i++) tot += s_red[i];
    const float rinv = 1.0f / tot;

    // Pass 3: normalize + zero the masked tail
    for (int t = threadIdx.x; t < Tnum; t += 256)
        out[b * Tnum + t] = (t < len) ? s_e[t] * rinv : 0.f;
}

// ---------------------------------------------------------------------------
extern "C" void kernel_launch(void* const* d_in, const int* in_sizes, int n_in,
                              void* d_out, int out_size)
{
    const float* hidden  = (const float*)d_in[0];      // [L,B,H]
    const float* eo      = (const float*)d_in[1];      // [T,B,H]
    const int*   enc_len = (const int*)d_in[2];        // [B] int32 OR int64 (auto-detected)
    const float* Wh      = (const float*)d_in[3];      // [H,H]
    const float* bh      = (const float*)d_in[4];      // [H]
    const float* Wo      = (const float*)d_in[5];      // [1,H]
    // d_in[6] = bo: uniform additive constant -> cancels in softmax, unused.
    float* out = (float*)d_out;                         // [B,T,1]

    proj_kernel<<<Hnum / 4, 256>>>(hidden, Wh, bh);
    energy_kernel<<<dim3(Tnum / 64, Bnum), 256>>>(eo, Wo);
    softmax_kernel<<<Bnum, 256>>>(enc_len, out);
}

// round 3
// speedup vs baseline: 1.1040x; 1.1040x over previous
#include <cuda_runtime.h>
#include <math.h>

#define Lnum 2
#define Bnum 32
#define Tnum 2048
#define Hnum 512

// Scratch (static device arrays — allocation-free per harness rules)
__device__ float g_hm[Bnum * Hnum];      // mean over L of hidden
__device__ float g_has[Bnum * Hnum];     // ha * 2*log2(e), pre-scaled for ex2
__device__ float g_energy[Bnum * Tnum];  // raw attention energies

__device__ __forceinline__ float ex2a(float x) {
    float y; asm("ex2.approx.f32 %0, %1;" : "=f"(y) : "f"(x)); return y;
}
__device__ __forceinline__ float rcpa(float x) {
    float y; asm("rcp.approx.f32 %0, %1;" : "=f"(y) : "f"(x)); return y;
}

#define C2LOG2E 2.8853900817779268f   // 2*log2(e)
#define LOG2E   1.4426950408889634f

// ---------------------------------------------------------------------------
// Kernel A0: hm[b,k] = 0.5*(hidden[0,b,k] + hidden[1,b,k]).  64KB, float4.
// ---------------------------------------------------------------------------
__global__ __launch_bounds__(256) void mean_kernel(const float* __restrict__ hidden)
{
    const int i = blockIdx.x * 256 + threadIdx.x;        // float4 index
    const float4* __restrict__ h0 = (const float4*)hidden;
    const float4* __restrict__ h1 = (const float4*)(hidden + Bnum * Hnum);
    float4 a = h0[i], b = h1[i];
    float4 r;
    r.x = 0.5f * (a.x + b.x); r.y = 0.5f * (a.y + b.y);
    r.z = 0.5f * (a.z + b.z); r.w = 0.5f * (a.w + b.w);
    ((float4*)g_hm)[i] = r;
}

// ---------------------------------------------------------------------------
// Kernel A1: ha[b,h] = sum_k hm[b,k]*Wh[h,k] + bh[h], pre-scaled by 2*log2e.
// grid=256 blocks: block handles 2 h-rows x all 32 b. Warp handles 4 b's with
// 8 independent accumulators (4b x 2h) in one 16-iter k-loop -> high ILP.
// ---------------------------------------------------------------------------
__global__ __launch_bounds__(256) void proj_kernel(
    const float* __restrict__ Wh,
    const float* __restrict__ bh)
{
    const int h0 = blockIdx.x * 2;
    __shared__ float s_w[2 * Hnum];
    {   // load 2 Wh rows (256 float4) coalesced
        const float4* __restrict__ w4 = (const float4*)(Wh + (size_t)h0 * Hnum);
        if (threadIdx.x < 256) ((float4*)s_w)[threadIdx.x] = w4[threadIdx.x];
    }
    __syncthreads();

    const int warp = threadIdx.x >> 5;
    const int lane = threadIdx.x & 31;
    const int b0 = warp * 4;

    const float* __restrict__ m0 = g_hm + (b0 + 0) * Hnum;
    const float* __restrict__ m1 = g_hm + (b0 + 1) * Hnum;
    const float* __restrict__ m2 = g_hm + (b0 + 2) * Hnum;
    const float* __restrict__ m3 = g_hm + (b0 + 3) * Hnum;

    float a00 = 0.f, a01 = 0.f, a02 = 0.f, a03 = 0.f;   // h0
    float a10 = 0.f, a11 = 0.f, a12 = 0.f, a13 = 0.f;   // h0+1
    #pragma unroll
    for (int k = lane; k < Hnum; k += 32) {
        float w0 = s_w[k];
        float w1 = s_w[Hnum + k];
        float v0 = m0[k], v1 = m1[k], v2 = m2[k], v3 = m3[k];
        a00 = fmaf(v0, w0, a00); a01 = fmaf(v1, w0, a01);
        a02 = fmaf(v2, w0, a02); a03 = fmaf(v3, w0, a03);
        a10 = fmaf(v0, w1, a10); a11 = fmaf(v1, w1, a11);
        a12 = fmaf(v2, w1, a12); a13 = fmaf(v3, w1, a13);
    }
    #pragma unroll
    for (int off = 16; off; off >>= 1) {
        a00 += __shfl_xor_sync(0xffffffffu, a00, off);
        a01 += __shfl_xor_sync(0xffffffffu, a01, off);
        a02 += __shfl_xor_sync(0xffffffffu, a02, off);
        a03 += __shfl_xor_sync(0xffffffffu, a03, off);
        a10 += __shfl_xor_sync(0xffffffffu, a10, off);
        a11 += __shfl_xor_sync(0xffffffffu, a11, off);
        a12 += __shfl_xor_sync(0xffffffffu, a12, off);
        a13 += __shfl_xor_sync(0xffffffffu, a13, off);
    }
    if (lane == 0) {
        const float b_h0 = bh[h0], b_h1 = bh[h0 + 1];
        g_has[(b0 + 0) * Hnum + h0]     = (a00 + b_h0) * C2LOG2E;
        g_has[(b0 + 1) * Hnum + h0]     = (a01 + b_h0) * C2LOG2E;
        g_has[(b0 + 2) * Hnum + h0]     = (a02 + b_h0) * C2LOG2E;
        g_has[(b0 + 3) * Hnum + h0]     = (a03 + b_h0) * C2LOG2E;
        g_has[(b0 + 0) * Hnum + h0 + 1] = (a10 + b_h1) * C2LOG2E;
        g_has[(b0 + 1) * Hnum + h0 + 1] = (a11 + b_h1) * C2LOG2E;
        g_has[(b0 + 2) * Hnum + h0 + 1] = (a12 + b_h1) * C2LOG2E;
        g_has[(b0 + 3) * Hnum + h0 + 1] = (a13 + b_h1) * C2LOG2E;
    }
}

// ---------------------------------------------------------------------------
// Kernel B: energy[b,t] = sum_h Wo[h] * tanh(eo[t,b,h] + ha[b,h])
// Streams the 128MB encoder_output exactly once. One warp per t; each lane
// handles 16 H-elements via 4x float4 coalesced loads.
// tanh(x) = (e^{2x}-1)/(e^{2x}+1), e^{2x} = ex2(C*x) with pre-scaled ha.
// ---------------------------------------------------------------------------
__global__ __launch_bounds__(256) void energy_kernel(
    const float* __restrict__ eo,
    const float* __restrict__ Wo)
{
    __shared__ float s_has[Hnum];
    __shared__ float s_wo[Hnum];
    const int b = blockIdx.y;
    const int tbase = blockIdx.x * 64;

    for (int i = threadIdx.x; i < Hnum; i += 256) {
        s_has[i] = g_has[b * Hnum + i];
        s_wo[i]  = Wo[i];
    }
    __syncthreads();

    const int warp = threadIdx.x >> 5;
    const int lane = threadIdx.x & 31;
    const float4* __restrict__ eo4 = (const float4*)eo;

    #pragma unroll 2
    for (int i = 0; i < 8; i++) {
        const int t = tbase + warp * 8 + i;
        const size_t base = ((size_t)t * Bnum + b) * (Hnum / 4);
        float acc = 0.f;
        #pragma unroll
        for (int j = 0; j < 4; j++) {
            const int k4 = j * 32 + lane;
            float4 e  = eo4[base + k4];
            float4 hs = *(const float4*)&s_has[k4 * 4];
            float4 wo = *(const float4*)&s_wo[k4 * 4];

            float arg, ex;
            arg = fmaf(e.x, C2LOG2E, hs.x);
            arg = fminf(fmaxf(arg, -80.f), 80.f);
            ex  = ex2a(arg);
            acc = fmaf((ex - 1.f) * wo.x, rcpa(ex + 1.f), acc);

            arg = fmaf(e.y, C2LOG2E, hs.y);
            arg = fminf(fmaxf(arg, -80.f), 80.f);
            ex  = ex2a(arg);
            acc = fmaf((ex - 1.f) * wo.y, rcpa(ex + 1.f), acc);

            arg = fmaf(e.z, C2LOG2E, hs.z);
            arg = fminf(fmaxf(arg, -80.f), 80.f);
            ex  = ex2a(arg);
            acc = fmaf((ex - 1.f) * wo.z, rcpa(ex + 1.f), acc);

            arg = fmaf(e.w, C2LOG2E, hs.w);
            arg = fminf(fmaxf(arg, -80.f), 80.f);
            ex  = ex2a(arg);
            acc = fmaf((ex - 1.f) * wo.w, rcpa(ex + 1.f), acc);
        }
        #pragma unroll
        for (int off = 16; off; off >>= 1)
            acc += __shfl_xor_sync(0xffffffffu, acc, off);
        if (lane == 0)
            g_energy[b * Tnum + t] = acc;
    }
}

// ---------------------------------------------------------------------------
// Kernel C: ragged masked softmax over T per batch row. bo cancels in
// softmax (uniform additive constant over the valid positions) -> dropped.
// 512 threads, 4 register-resident energies per thread -> short passes.
//
// enc_len dtype auto-detect (JAX silently downgrades int64->int32 unless
// x64 is enabled): valid lengths >= 1, so word[1]==0 iff the buffer is
// little-endian int64 (word[1] = high half of element 0).
// ---------------------------------------------------------------------------
__global__ __launch_bounds__(512) void softmax_kernel(
    const int* __restrict__ enc_len_w,
    float* __restrict__ out)
{
    const int b = blockIdx.x;
    const bool is64 = (enc_len_w[1] == 0);
    const int len = is64 ? enc_len_w[2 * b] : enc_len_w[b];   // in [1, T]

    __shared__ float s_red[16];
    const int warp = threadIdx.x >> 5;
    const int lane = threadIdx.x & 31;

    // Each thread owns 4 consecutive elements via one float4 load
    const int t0 = threadIdx.x * 4;
    float4 e = *(const float4*)&g_energy[b * Tnum + t0];
    float v0 = e.x, v1 = e.y, v2 = e.z, v3 = e.w;

    // Masked max
    float m = -3.0e38f;
    if (t0 + 0 < len) m = fmaxf(m, v0);
    if (t0 + 1 < len) m = fmaxf(m, v1);
    if (t0 + 2 < len) m = fmaxf(m, v2);
    if (t0 + 3 < len) m = fmaxf(m, v3);
    #pragma unroll
    for (int off = 16; off; off >>= 1)
        m = fmaxf(m, __shfl_xor_sync(0xffffffffu, m, off));
    if (lane == 0) s_red[warp] = m;
    __syncthreads();
    m = s_red[0];
    #pragma unroll
    for (int i = 1; i < 16; i++) m = fmaxf(m, s_red[i]);
    __syncthreads();

    // exp + masked sum
    float p0 = (t0 + 0 < len) ? ex2a((v0 - m) * LOG2E) : 0.f;
    float p1 = (t0 + 1 < len) ? ex2a((v1 - m) * LOG2E) : 0.f;
    float p2 = (t0 + 2 < len) ? ex2a((v2 - m) * LOG2E) : 0.f;
    float p3 = (t0 + 3 < len) ? ex2a((v3 - m) * LOG2E) : 0.f;
    float s = (p0 + p1) + (p2 + p3);
    #pragma unroll
    for (int off = 16; off; off >>= 1)
        s += __shfl_xor_sync(0xffffffffu, s, off);
    if (lane == 0) s_red[warp] = s;
    __syncthreads();
    float tot = 0.f;
    #pragma unroll
    for (int i = 0; i < 16; i++) tot += s_red[i];
    const float rinv = 1.0f / tot;

    float4 o;
    o.x = p0 * rinv; o.y = p1 * rinv; o.z = p2 * rinv; o.w = p3 * rinv;
    *(float4*)&out[b * Tnum + t0] = o;
}

// ---------------------------------------------------------------------------
extern "C" void kernel_launch(void* const* d_in, const int* in_sizes, int n_in,
                              void* d_out, int out_size)
{
    const float* hidden  = (const float*)d_in[0];      // [L,B,H]
    const float* eo      = (const float*)d_in[1];      // [T,B,H]
    const int*   enc_len = (const int*)d_in[2];        // [B] int32 OR int64 (auto-detected)
    const float* Wh      = (const float*)d_in[3];      // [H,H]
    const float* bh      = (const float*)d_in[4];      // [H]
    const float* Wo      = (const float*)d_in[5];      // [1,H]
    // d_in[6] = bo: uniform additive constant -> cancels in softmax, unused.
    float* out = (float*)d_out;                         // [B,T,1]

    mean_kernel<<<(Bnum * Hnum / 4) / 256, 256>>>(hidden);
    proj_kernel<<<Hnum / 2, 256>>>(Wh, bh);
    energy_kernel<<<dim3(Tnum / 64, Bnum), 256>>>(eo, Wo);
    softmax_kernel<<<Bnum, 512>>>(enc_len, out);
}

// round 4
// speedup vs baseline: 1.4772x; 1.3380x over previous
#include <cuda_runtime.h>
#include <math.h>

#define Lnum 2
#define Bnum 32
#define Tnum 2048
#define Hnum 512

// Scratch (static device arrays — allocation-free per harness rules)
__device__ float g_hm[Bnum * Hnum];      // mean over L of hidden
__device__ float g_has[Bnum * Hnum];     // ha * 2*log2(e), pre-scaled for ex2
__device__ float g_p[Bnum * Tnum];       // unnormalized softmax numerators
__device__ float g_psum[Bnum * 32];      // per-(b, t-chunk) partial sums

__device__ __forceinline__ float ex2a(float x) {
    float y; asm("ex2.approx.f32 %0, %1;" : "=f"(y) : "f"(x)); return y;
}
__device__ __forceinline__ float rcpa(float x) {
    float y; asm("rcp.approx.f32 %0, %1;" : "=f"(y) : "f"(x)); return y;
}

#define C2LOG2E 2.8853900817779268f   // 2*log2(e)
#define LOG2E   1.4426950408889634f

// ---------------------------------------------------------------------------
// Kernel A0: hm[b,k] = 0.5*(hidden[0,b,k] + hidden[1,b,k]).  64KB, float4.
// ---------------------------------------------------------------------------
__global__ __launch_bounds__(256) void mean_kernel(const float* __restrict__ hidden)
{
    const int i = blockIdx.x * 256 + threadIdx.x;        // float4 index
    const float4* __restrict__ h0 = (const float4*)hidden;
    const float4* __restrict__ h1 = (const float4*)(hidden + Bnum * Hnum);
    float4 a = h0[i], b = h1[i];
    float4 r;
    r.x = 0.5f * (a.x + b.x); r.y = 0.5f * (a.y + b.y);
    r.z = 0.5f * (a.z + b.z); r.w = 0.5f * (a.w + b.w);
    ((float4*)g_hm)[i] = r;
}

// ---------------------------------------------------------------------------
// Kernel A1: ha[b,h] = sum_k hm[b,k]*Wh[h,k] + bh[h], pre-scaled by 2*log2e.
// Block handles 2 h-rows x all 32 b; warp: 4 b x 2 h = 8 accumulators (ILP).
// ---------------------------------------------------------------------------
__global__ __launch_bounds__(256) void proj_kernel(
    const float* __restrict__ Wh,
    const float* __restrict__ bh)
{
    const int h0 = blockIdx.x * 2;
    __shared__ float s_w[2 * Hnum];
    {
        const float4* __restrict__ w4 = (const float4*)(Wh + (size_t)h0 * Hnum);
        if (threadIdx.x < 256) ((float4*)s_w)[threadIdx.x] = w4[threadIdx.x];
    }
    __syncthreads();

    const int warp = threadIdx.x >> 5;
    const int lane = threadIdx.x & 31;
    const int b0 = warp * 4;

    const float* __restrict__ m0 = g_hm + (b0 + 0) * Hnum;
    const float* __restrict__ m1 = g_hm + (b0 + 1) * Hnum;
    const float* __restrict__ m2 = g_hm + (b0 + 2) * Hnum;
    const float* __restrict__ m3 = g_hm + (b0 + 3) * Hnum;

    float a00 = 0.f, a01 = 0.f, a02 = 0.f, a03 = 0.f;
    float a10 = 0.f, a11 = 0.f, a12 = 0.f, a13 = 0.f;
    #pragma unroll
    for (int k = lane; k < Hnum; k += 32) {
        float w0 = s_w[k];
        float w1 = s_w[Hnum + k];
        float v0 = m0[k], v1 = m1[k], v2 = m2[k], v3 = m3[k];
        a00 = fmaf(v0, w0, a00); a01 = fmaf(v1, w0, a01);
        a02 = fmaf(v2, w0, a02); a03 = fmaf(v3, w0, a03);
        a10 = fmaf(v0, w1, a10); a11 = fmaf(v1, w1, a11);
        a12 = fmaf(v2, w1, a12); a13 = fmaf(v3, w1, a13);
    }
    #pragma unroll
    for (int off = 16; off; off >>= 1) {
        a00 += __shfl_xor_sync(0xffffffffu, a00, off);
        a01 += __shfl_xor_sync(0xffffffffu, a01, off);
        a02 += __shfl_xor_sync(0xffffffffu, a02, off);
        a03 += __shfl_xor_sync(0xffffffffu, a03, off);
        a10 += __shfl_xor_sync(0xffffffffu, a10, off);
        a11 += __shfl_xor_sync(0xffffffffu, a11, off);
        a12 += __shfl_xor_sync(0xffffffffu, a12, off);
        a13 += __shfl_xor_sync(0xffffffffu, a13, off);
    }
    if (lane == 0) {
        const float b_h0 = bh[h0], b_h1 = bh[h0 + 1];
        g_has[(b0 + 0) * Hnum + h0]     = (a00 + b_h0) * C2LOG2E;
        g_has[(b0 + 1) * Hnum + h0]     = (a01 + b_h0) * C2LOG2E;
        g_has[(b0 + 2) * Hnum + h0]     = (a02 + b_h0) * C2LOG2E;
        g_has[(b0 + 3) * Hnum + h0]     = (a03 + b_h0) * C2LOG2E;
        g_has[(b0 + 0) * Hnum + h0 + 1] = (a10 + b_h1) * C2LOG2E;
        g_has[(b0 + 1) * Hnum + h0 + 1] = (a11 + b_h1) * C2LOG2E;
        g_has[(b0 + 2) * Hnum + h0 + 1] = (a12 + b_h1) * C2LOG2E;
        g_has[(b0 + 3) * Hnum + h0 + 1] = (a13 + b_h1) * C2LOG2E;
    }
}

// ---------------------------------------------------------------------------
// Kernel B: p[b,t] = exp( sum_h Wo[h]*tanh(eo[t,b,h]+ha[b,h]) ) for t<len,
// else 0. RAGGED SKIP: eo rows for t >= len are never loaded (halves the
// 128MB stream in expectation). No-max exp is safe: |energy| <= sum|Wo| ~ 18
// so exp stays within fp32 range with >60 e-units of margin.
// Per-(b,chunk) partial sums written deterministically (no atomics).
// tanh(x) = (e^{2x}-1)/(e^{2x}+1), e^{2x} = ex2(C*x) with pre-scaled ha.
// ---------------------------------------------------------------------------
__global__ __launch_bounds__(256) void energy_kernel(
    const float* __restrict__ eo,
    const float* __restrict__ Wo,
    const int* __restrict__ enc_len_w)
{
    const int b = blockIdx.y;
    const int tbase = blockIdx.x * 64;
    // enc_len dtype auto-detect (JAX may canonicalize int64->int32):
    // lengths >= 1, so word[1]==0 iff buffer is little-endian int64.
    const bool is64 = (enc_len_w[1] == 0);
    const int len = is64 ? enc_len_w[2 * b] : enc_len_w[b];

    if (tbase >= len) {   // whole chunk masked: zeros, no eo traffic
        if (threadIdx.x < 64) g_p[b * Tnum + tbase + threadIdx.x] = 0.f;
        if (threadIdx.x == 0) g_psum[b * 32 + blockIdx.x] = 0.f;
        return;
    }

    __shared__ float s_has[Hnum];
    __shared__ float s_wo[Hnum];
    __shared__ float s_ws[8];

    for (int i = threadIdx.x; i < Hnum; i += 256) {
        s_has[i] = g_has[b * Hnum + i];
        s_wo[i]  = Wo[i];
    }
    __syncthreads();

    const int warp = threadIdx.x >> 5;
    const int lane = threadIdx.x & 31;
    const float4* __restrict__ eo4 = (const float4*)eo;

    float wsum = 0.f;
    #pragma unroll 2
    for (int i = 0; i < 8; i++) {
        const int t = tbase + warp * 8 + i;
        if (t < len) {
            const size_t base = ((size_t)t * Bnum + b) * (Hnum / 4);
            float acc = 0.f;
            #pragma unroll
            for (int j = 0; j < 4; j++) {
                const int k4 = j * 32 + lane;
                float4 e  = __ldcs(&eo4[base + k4]);
                float4 hs = *(const float4*)&s_has[k4 * 4];
                float4 wo = *(const float4*)&s_wo[k4 * 4];

                float arg, ex;
                arg = fmaf(e.x, C2LOG2E, hs.x);
                arg = fminf(fmaxf(arg, -80.f), 80.f);
                ex  = ex2a(arg);
                acc = fmaf((ex - 1.f) * wo.x, rcpa(ex + 1.f), acc);

                arg = fmaf(e.y, C2LOG2E, hs.y);
                arg = fminf(fmaxf(arg, -80.f), 80.f);
                ex  = ex2a(arg);
                acc = fmaf((ex - 1.f) * wo.y, rcpa(ex + 1.f), acc);

                arg = fmaf(e.z, C2LOG2E, hs.z);
                arg = fminf(fmaxf(arg, -80.f), 80.f);
                ex  = ex2a(arg);
                acc = fmaf((ex - 1.f) * wo.z, rcpa(ex + 1.f), acc);

                arg = fmaf(e.w, C2LOG2E, hs.w);
                arg = fminf(fmaxf(arg, -80.f), 80.f);
                ex  = ex2a(arg);
                acc = fmaf((ex - 1.f) * wo.w, rcpa(ex + 1.f), acc);
            }
            #pragma unroll
            for (int off = 16; off; off >>= 1)
                acc += __shfl_xor_sync(0xffffffffu, acc, off);
            float p = ex2a(acc * LOG2E);     // exp(energy), no-max (bounded)
            if (lane == 0) {
                g_p[b * Tnum + t] = p;
                wsum += p;
            }
        } else if (lane == 0) {
            g_p[b * Tnum + t] = 0.f;
        }
    }
    if (lane == 0) s_ws[warp] = wsum;
    __syncthreads();
    if (threadIdx.x == 0) {
        float tot = 0.f;
        #pragma unroll
        for (int i = 0; i < 8; i++) tot += s_ws[i];
        g_psum[b * 32 + blockIdx.x] = tot;
    }
}

// ---------------------------------------------------------------------------
// Kernel C: out[b,t] = p[b,t] / sum_chunks psum[b,:].  Deterministic
// 32-partial reduction per block, then float4 elementwise scale.
// ---------------------------------------------------------------------------
__global__ __launch_bounds__(128) void normalize_kernel(float* __restrict__ out)
{
    const int b = blockIdx.y;
    __shared__ float s_rinv;

    if (threadIdx.x < 32) {
        float v = g_psum[b * 32 + threadIdx.x];
        #pragma unroll
        for (int off = 16; off; off >>= 1)
            v += __shfl_xor_sync(0xffffffffu, v, off);
        if (threadIdx.x == 0) s_rinv = 1.0f / v;
    }
    __syncthreads();
    const float rinv = s_rinv;

    const int t0 = (blockIdx.x * 128 + threadIdx.x) * 4;
    float4 p = *(const float4*)&g_p[b * Tnum + t0];
    float4 o;
    o.x = p.x * rinv; o.y = p.y * rinv; o.z = p.z * rinv; o.w = p.w * rinv;
    *(float4*)&out[b * Tnum + t0] = o;
}

// ---------------------------------------------------------------------------
extern "C" void kernel_launch(void* const* d_in, const int* in_sizes, int n_in,
                              void* d_out, int out_size)
{
    const float* hidden  = (const float*)d_in[0];      // [L,B,H]
    const float* eo      = (const float*)d_in[1];      // [T,B,H]
    const int*   enc_len = (const int*)d_in[2];        // [B] int32 OR int64 (auto-detected)
    const float* Wh      = (const float*)d_in[3];      // [H,H]
    const float* bh      = (const float*)d_in[4];      // [H]
    const float* Wo      = (const float*)d_in[5];      // [1,H]
    // d_in[6] = bo: uniform additive constant -> cancels in softmax, unused.
    float* out = (float*)d_out;                         // [B,T,1]

    mean_kernel<<<(Bnum * Hnum / 4) / 256, 256>>>(hidden);
    proj_kernel<<<Hnum / 2, 256>>>(Wh, bh);
    energy_kernel<<<dim3(Tnum / 64, Bnum), 256>>>(eo, Wo, enc_len);
    normalize_kernel<<<dim3(Tnum / 512, Bnum), 128>>>(out);
}